// round 9
// baseline (speedup 1.0000x reference)
#include <cuda_runtime.h>
#include <cstdint>

#define CCH    33
#define KSZ    2112      // 33*8*8 floats per crop
#define FEAT   107
#define IMG    65536     // 256*256
#define QP     4         // crops per block
#define NPG    9         // patch groups (36/QP)
#define NTHR   256
#define SEGS   (QP * CCH * 8 * 3)      // 3168 lane-loads (3 segs per row)

// SHIFTS / 255 exactly as the reference table (note duplicated [0,8] at j=6)
__constant__ float c_shift[9][2] = {
  {-8.f/255.f,  0.f/255.f}, {-8.f/255.f,  8.f/255.f}, { 0.f/255.f,  8.f/255.f},
  { 8.f/255.f,  8.f/255.f}, { 8.f/255.f,  0.f/255.f}, { 8.f/255.f, -8.f/255.f},
  { 0.f/255.f,  8.f/255.f}, {-8.f/255.f, -8.f/255.f}, { 0.f/255.f,  0.f/255.f}
};

__device__ float g_patch_feat[32 * 36 * 33];
__device__ int   g_cnt[32];            // monotonic; %NPG==NPG-1 triggers tail

// ---------------------------------------------------------------------------
// threefry2x32 (JAX partitionable)
// ---------------------------------------------------------------------------
__device__ __forceinline__ void threefry2x32(uint32_t k0, uint32_t k1,
                                             uint32_t x0, uint32_t x1,
                                             uint32_t& o0, uint32_t& o1)
{
  uint32_t ks[3] = {k0, k1, k0 ^ k1 ^ 0x1BD11BDAu};
  x0 += ks[0]; x1 += ks[1];
  const int R[2][4] = {{13, 15, 26, 6}, {17, 29, 16, 24}};
#pragma unroll
  for (int i = 0; i < 5; ++i) {
#pragma unroll
    for (int r = 0; r < 4; ++r) {
      x0 += x1;
      int rr = R[i & 1][r];
      x1 = (x1 << rr) | (x1 >> (32 - rr));
      x1 ^= x0;
    }
    x0 += ks[(i + 1) % 3];
    x1 += ks[(i + 2) % 3] + (uint32_t)(i + 1);
  }
  o0 = x0; o1 = x1;
}

__device__ __forceinline__ float tf_uniform(uint32_t k0, uint32_t k1, uint32_t g)
{
  uint32_t y0, y1;
  threefry2x32(k0, k1, 0u, g, y0, y1);
  uint32_t bits = y0 ^ y1;
  return __uint_as_float((bits >> 9) | 0x3f800000u) - 1.0f;
}

// ---------------------------------------------------------------------------
// Fused kernel. grid (NPG, 32) x 256 threads, 8 warps x 4 output rows.
// ---------------------------------------------------------------------------
__global__ __launch_bounds__(NTHR, 3)
void fused_kernel(const float* __restrict__ d, const float* __restrict__ x,
                  const float* __restrict__ conv_w, const float* __restrict__ conv_b,
                  const float* __restrict__ H,  const float* __restrict__ T,
                  const float* __restrict__ W,
                  const float* __restrict__ l1w, const float* __restrict__ l1b,
                  const float* __restrict__ l2w, const float* __restrict__ l2b,
                  float* __restrict__ out)
{
  __shared__ float smemf[QP * KSZ];    // crops; aliased by tail (needs 6088)
  __shared__ int s_ix[QP], s_iy[QP];
  __shared__ int s_flag;

  const int pg  = blockIdx.x;
  const int b   = blockIdx.y;
  const int tid = threadIdx.x;
  const int warp = tid >> 5, lane = tid & 31;

  // ---- crop coordinates (parallel replay, exact fp order) -------------------
  if (tid < 36) {
    const int idx = (tid / 9) * (tid % 9);
    float lx = x[b * 8 + (idx / 9) * 2 + 0];
    float ly = x[b * 8 + (idx / 9) * 2 + 1];
#pragma unroll
    for (int st = 0; st < 36; ++st) {
      int i = st / 9, j = st % 9;
      if (st <= tid && i * j == idx) { lx += c_shift[j][0]; ly += c_shift[j][1]; }
    }
    int rel = tid - pg * QP;
    if (rel >= 0 && rel < QP) {
      int ix = (int)rintf(lx * 255.f);
      int iy = (int)rintf((ly + 1.0f) * 255.f);
      s_ix[rel] = min(max(ix, 0), 255);
      s_iy[rel] = min(max(iy, 0), 255);
    }
  }
  __syncthreads();

  // ---- gather: seg-coalesced. lane-load = (q, c, h, seg) --------------------
  const float* db = d + (size_t)b * CCH * IMG;
#pragma unroll 4
  for (int u = 0; u < 13; ++u) {
    int rid = tid + u * NTHR;
    if (rid < SEGS) {
      int q    = rid / 792;            // 792 = 264*3
      int rem  = rid - q * 792;
      int c    = rem / 24;
      int hs   = rem - c * 24;
      int h    = hs / 3, seg = hs - h * 3;
      int r    = s_ix[q] - 4 + h;
      int col0 = s_iy[q] - 4;
      int a    = col0 & 3;
      int sb   = (col0 - a) + seg * 4;
      float4 v = {0.f, 0.f, 0.f, 0.f};
      if ((unsigned)r < 256u && (unsigned)sb < 256u)
        v = *(const float4*)(db + c * IMG + r * 256 + sb);
      int w0 = seg * 4 - a;
      float* dst = smemf + q * KSZ + c * 64 + h * 8;
      if ((unsigned)(w0 + 0) < 8u) dst[w0 + 0] = v.x;
      if ((unsigned)(w0 + 1) < 8u) dst[w0 + 1] = v.y;
      if ((unsigned)(w0 + 2) < 8u) dst[w0 + 2] = v.z;
      if ((unsigned)(w0 + 3) < 8u) dst[w0 + 3] = v.w;
    }
  }

  // ---- prefetch first weight chunk BEFORE sync ------------------------------
  const float4* w4 = (const float4*)conv_w;
  float4 wv_c[4], wv_n[4], wx_c = {0,0,0,0}, wx_n = {0,0,0,0};
#pragma unroll
  for (int j = 0; j < 4; ++j) wv_c[j] = __ldg(w4 + (warp + j * 8) * 528 + lane);
  if (warp == 0) wx_c = __ldg(w4 + 32 * 528 + lane);

  __syncthreads();

  // ---- conv mainloop: 8 warps x 4 rows x 4 crops ---------------------------
  float acc[4][QP], accx[QP];
#pragma unroll
  for (int j = 0; j < 4; ++j)
#pragma unroll
    for (int q = 0; q < QP; ++q) acc[j][q] = 0.f;
#pragma unroll
  for (int q = 0; q < QP; ++q) accx[q] = 0.f;

#pragma unroll 1
  for (int c = 0; c < 16; ++c) {
    int k4 = lane + c * 32;
    float4 cv[QP];
#pragma unroll
    for (int q = 0; q < QP; ++q)
      cv[q] = *(const float4*)(smemf + q * KSZ + k4 * 4);

    int kn = lane + (c + 1) * 32;
    if (kn > 527) kn = 527;
#pragma unroll
    for (int j = 0; j < 4; ++j) wv_n[j] = __ldg(w4 + (warp + j * 8) * 528 + kn);
    if (warp == 0) wx_n = __ldg(w4 + 32 * 528 + kn);

#pragma unroll
    for (int j = 0; j < 4; ++j)
#pragma unroll
      for (int q = 0; q < QP; ++q) {
        acc[j][q] = fmaf(cv[q].x, wv_c[j].x, acc[j][q]);
        acc[j][q] = fmaf(cv[q].y, wv_c[j].y, acc[j][q]);
        acc[j][q] = fmaf(cv[q].z, wv_c[j].z, acc[j][q]);
        acc[j][q] = fmaf(cv[q].w, wv_c[j].w, acc[j][q]);
      }
    if (warp == 0) {
#pragma unroll
      for (int q = 0; q < QP; ++q) {
        accx[q] = fmaf(cv[q].x, wx_c.x, accx[q]);
        accx[q] = fmaf(cv[q].y, wx_c.y, accx[q]);
        accx[q] = fmaf(cv[q].z, wx_c.z, accx[q]);
        accx[q] = fmaf(cv[q].w, wx_c.w, accx[q]);
      }
    }
#pragma unroll
    for (int j = 0; j < 4; ++j) wv_c[j] = wv_n[j];
    wx_c = wx_n;
  }
  if (lane < 16) {   // epilogue: k4 in [512,528)
    int k4 = lane + 512;
    float4 cv[QP];
#pragma unroll
    for (int q = 0; q < QP; ++q)
      cv[q] = *(const float4*)(smemf + q * KSZ + k4 * 4);
#pragma unroll
    for (int j = 0; j < 4; ++j)
#pragma unroll
      for (int q = 0; q < QP; ++q) {
        acc[j][q] = fmaf(cv[q].x, wv_c[j].x, acc[j][q]);
        acc[j][q] = fmaf(cv[q].y, wv_c[j].y, acc[j][q]);
        acc[j][q] = fmaf(cv[q].z, wv_c[j].z, acc[j][q]);
        acc[j][q] = fmaf(cv[q].w, wv_c[j].w, acc[j][q]);
      }
    if (warp == 0) {
#pragma unroll
      for (int q = 0; q < QP; ++q) {
        accx[q] = fmaf(cv[q].x, wx_c.x, accx[q]);
        accx[q] = fmaf(cv[q].y, wx_c.y, accx[q]);
        accx[q] = fmaf(cv[q].z, wx_c.z, accx[q]);
        accx[q] = fmaf(cv[q].w, wx_c.w, accx[q]);
      }
    }
  }

  // ---- reduce + write patch_feat -------------------------------------------
  float* pfb = g_patch_feat + ((size_t)b * 36 + pg * QP) * 33;
#pragma unroll
  for (int j = 0; j < 4; ++j) {
    int o = warp + j * 8;
#pragma unroll
    for (int q = 0; q < QP; ++q) {
      float s = acc[j][q];
#pragma unroll
      for (int sh = 16; sh; sh >>= 1) s += __shfl_xor_sync(0xffffffffu, s, sh);
      if (lane == 0) pfb[q * 33 + o] = s + conv_b[o];
    }
  }
  if (warp == 0) {
#pragma unroll
    for (int q = 0; q < QP; ++q) {
      float s = accx[q];
#pragma unroll
      for (int sh = 16; sh; sh >>= 1) s += __shfl_xor_sync(0xffffffffu, s, sh);
      if (lane == 0) pfb[q * 33 + 32] = s + conv_b[32];
    }
  }

  // ---- last-block-per-batch election ---------------------------------------
  __threadfence();
  __syncthreads();
  if (tid == 0) {
    int old = atomicAdd(&g_cnt[b], 1);
    s_flag = ((old % NPG) == (NPG - 1)) ? 1 : 0;
  }
  __syncthreads();
  if (!s_flag) return;

  // ======================= TAIL (winner block per batch) =====================
  float* gin = smemf;                 // [0, 3852)
  float* psm = smemf + 3872;          // params: 1924 floats
  float* lhv = smemf + 5800;          // 72
  float* Am  = smemf + 5880;          // 64
  float* M1m = smemf + 5944;          // 144

  uint32_t k10, k11, k20, k21;
  threefry2x32(0u, 42u, 0u, 0u, k10, k11);
  threefry2x32(0u, 42u, 0u, 1u, k20, k21);

  // phase 1: params + lh + patch_feat->gin (independent)
  for (int e = tid; e < 144; e += NTHR) psm[e] = T[e];
  for (int e = tid; e < 576; e += NTHR) psm[144 + e] = H[e];
  if (tid < 16)  psm[720 + tid] = W[tid];
  for (int e = tid; e < 214; e += NTHR) psm[736 + e] = l1w[e];
  if (tid < 2)   psm[950 + tid] = l1b[tid];
  for (int e = tid; e < 963; e += NTHR) psm[952 + e] = l2w[e];
  if (tid < 9)   psm[1915 + tid] = l2b[tid];

  if (tid < 36) {
    float lx = x[b * 8 + (tid / 9) * 2 + 0];
    float ly = x[b * 8 + (tid / 9) * 2 + 1];
#pragma unroll
    for (int st = 0; st < 36; ++st) {
      int i = st / 9, j = st % 9;
      if (i * j == tid) { lx += c_shift[j][0]; ly += c_shift[j][1]; }
    }
    lhv[tid * 2 + 0] = lx; lhv[tid * 2 + 1] = ly;
    gin[tid * FEAT + 105] = lx;
    gin[tid * FEAT + 106] = ly;
  }
  for (int e = tid; e < 1188; e += NTHR)
    gin[(e / 33) * FEAT + (e % 33)] = __ldcg(&g_patch_feat[b * 1188 + e]);
  __syncthreads();

  // phase 2: shape feats + A
  for (int e = tid; e < 36 * 72; e += NTHR) {
    int n = e / 72, qq = e % 72, m = qq >> 1, kk = qq & 1;
    gin[n * FEAT + 33 + qq] = lhv[m * 2 + kk] - lhv[n * 2 + kk];
  }
  if (tid >= 64 && tid < 128) {
    int p = (tid - 64) >> 4, h = (tid - 64) & 15;
    float wh = psm[720 + h], s = 0.f;
    for (int n = 0; n < 36; ++n) s += psm[p * 36 + n] * (psm[144 + n * 16 + h] * wh);
    Am[p * 16 + h] = s;
  }
  __syncthreads();

  // phase 3: M1
  if (tid < 144) {
    int p = tid / 36, n = tid % 36;
    float s = 0.f;
#pragma unroll
    for (int h = 0; h < 16; ++h) s += Am[p * 16 + h] * psm[144 + n * 16 + h];
    M1m[p * 36 + n] = s;
  }
  __syncthreads();

  // phase 4: message + dropout + heads (warp p = point p)
  if (warp < 4) {
    const int p = warp;
    float hacc[11];
#pragma unroll
    for (int o = 0; o < 11; ++o) hacc[o] = 0.f;
#pragma unroll
    for (int r = 0; r < 4; ++r) {
      int f = lane + 32 * r;
      if (f < FEAT) {
        float s = 0.f;
#pragma unroll
        for (int n = 0; n < 36; ++n) s = fmaf(M1m[p * 36 + n], gin[n * FEAT + f], s);
        uint32_t g = (uint32_t)((b * 4 + p) * FEAT + f);
        float u1 = tf_uniform(k10, k11, g);
        float u2 = tf_uniform(k20, k21, g);
        float x1 = (u1 < 0.9f) ? s / 0.9f : 0.f;
        float x2 = (u2 < 0.9f) ? s / 0.9f : 0.f;
        hacc[0] = fmaf(x1, psm[736 + f], hacc[0]);
        hacc[1] = fmaf(x1, psm[736 + FEAT + f], hacc[1]);
#pragma unroll
        for (int j = 0; j < 9; ++j)
          hacc[2 + j] = fmaf(x2, psm[952 + j * FEAT + f], hacc[2 + j]);
      }
    }
#pragma unroll
    for (int o = 0; o < 11; ++o)
#pragma unroll
      for (int sh = 16; sh; sh >>= 1)
        hacc[o] += __shfl_xor_sync(0xffffffffu, hacc[o], sh);

    if (lane == 0) {
      float off0 = 1.f / (1.f + expf(-(hacc[0] + psm[950])));
      float off1 = 1.f / (1.f + expf(-(hacc[1] + psm[951])));
      float lg[9], mx = -1e30f;
#pragma unroll
      for (int j = 0; j < 9; ++j) { lg[j] = hacc[2 + j] + psm[1915 + j]; mx = fmaxf(mx, lg[j]); }
      float den = 0.f, s0 = 0.f, s1 = 0.f;
#pragma unroll
      for (int j = 0; j < 9; ++j) {
        float e = expf(lg[j] - mx);
        den += e;
        s0 += e * c_shift[j][0];
        s1 += e * c_shift[j][1];
      }
      s0 /= den; s1 /= den;
      out[b * 8 + p * 2 + 0] = (x[b * 8 + p * 2 + 0] + off0 * s0) * 255.f;
      out[b * 8 + p * 2 + 1] = (x[b * 8 + p * 2 + 1] + off1 * s1) * 255.f;
    }
  }
}

// ---------------------------------------------------------------------------
extern "C" void kernel_launch(void* const* d_in, const int* in_sizes, int n_in,
                              void* d_out, int out_size)
{
  const float* d      = (const float*)d_in[0];
  const float* x      = (const float*)d_in[1];
  const float* conv_w = (const float*)d_in[2];
  const float* conv_b = (const float*)d_in[3];
  const float* H      = (const float*)d_in[4];
  const float* T      = (const float*)d_in[5];
  const float* W      = (const float*)d_in[6];
  const float* l1w    = (const float*)d_in[7];
  const float* l1b    = (const float*)d_in[8];
  const float* l2w    = (const float*)d_in[9];
  const float* l2b    = (const float*)d_in[10];
  float* out = (float*)d_out;

  dim3 grid(NPG, 32);
  fused_kernel<<<grid, NTHR>>>(d, x, conv_w, conv_b,
                               H, T, W, l1w, l1b, l2w, l2b, out);
}

// round 10
// speedup vs baseline: 1.0286x; 1.0286x over previous
#include <cuda_runtime.h>
#include <cstdint>

#define CCH    33
#define KSZ    2112      // 33*8*8 floats per crop
#define FEAT   107
#define IMG    65536     // 256*256
#define QP     4         // crops per block
#define NPG    9         // patch groups (36/QP)
#define NTHR   512
#define SEGS   (QP * CCH * 8 * 3)      // 3168 lane-loads (3 segs per row)

// SHIFTS / 255 exactly as the reference table (note duplicated [0,8] at j=6)
__constant__ float c_shift[9][2] = {
  {-8.f/255.f,  0.f/255.f}, {-8.f/255.f,  8.f/255.f}, { 0.f/255.f,  8.f/255.f},
  { 8.f/255.f,  8.f/255.f}, { 8.f/255.f,  0.f/255.f}, { 8.f/255.f, -8.f/255.f},
  { 0.f/255.f,  8.f/255.f}, {-8.f/255.f, -8.f/255.f}, { 0.f/255.f,  0.f/255.f}
};

__device__ float g_patch_feat[32 * 36 * 33];
__device__ int   g_cnt[32];            // monotonic; %NPG==NPG-1 triggers tail

// ---------------------------------------------------------------------------
// threefry2x32 (JAX partitionable)
// ---------------------------------------------------------------------------
__device__ __forceinline__ void threefry2x32(uint32_t k0, uint32_t k1,
                                             uint32_t x0, uint32_t x1,
                                             uint32_t& o0, uint32_t& o1)
{
  uint32_t ks[3] = {k0, k1, k0 ^ k1 ^ 0x1BD11BDAu};
  x0 += ks[0]; x1 += ks[1];
  const int R[2][4] = {{13, 15, 26, 6}, {17, 29, 16, 24}};
#pragma unroll
  for (int i = 0; i < 5; ++i) {
#pragma unroll
    for (int r = 0; r < 4; ++r) {
      x0 += x1;
      int rr = R[i & 1][r];
      x1 = (x1 << rr) | (x1 >> (32 - rr));
      x1 ^= x0;
    }
    x0 += ks[(i + 1) % 3];
    x1 += ks[(i + 2) % 3] + (uint32_t)(i + 1);
  }
  o0 = x0; o1 = x1;
}

__device__ __forceinline__ float tf_uniform(uint32_t k0, uint32_t k1, uint32_t g)
{
  uint32_t y0, y1;
  threefry2x32(k0, k1, 0u, g, y0, y1);
  uint32_t bits = y0 ^ y1;
  return __uint_as_float((bits >> 9) | 0x3f800000u) - 1.0f;
}

// ---------------------------------------------------------------------------
// Fused kernel. grid (NPG, 32) x 512 threads.
// 16 warps = 8 row-groups x 2 K-halves. rg owns rows {rg,rg+8,rg+16,rg+24}.
// ---------------------------------------------------------------------------
__global__ __launch_bounds__(NTHR, 2)
void fused_kernel(const float* __restrict__ d, const float* __restrict__ x,
                  const float* __restrict__ conv_w, const float* __restrict__ conv_b,
                  const float* __restrict__ H,  const float* __restrict__ T,
                  const float* __restrict__ W,
                  const float* __restrict__ l1w, const float* __restrict__ l1b,
                  const float* __restrict__ l2w, const float* __restrict__ l2b,
                  float* __restrict__ out)
{
  __shared__ float smemf[QP * KSZ];    // crops; aliased by tail
  __shared__ float s_part[33 * QP];    // half-1 partials
  __shared__ float s_part32[QP];
  __shared__ int s_ix[QP], s_iy[QP];
  __shared__ int s_flag;

  const int pg  = blockIdx.x;
  const int b   = blockIdx.y;
  const int tid = threadIdx.x;
  const int warp = tid >> 5, lane = tid & 31;
  const int rg   = warp & 7, half = warp >> 3;

  // ---- crop coordinates (parallel replay, exact fp order) -------------------
  if (tid < 36) {
    const int idx = (tid / 9) * (tid % 9);
    float lx = x[b * 8 + (idx / 9) * 2 + 0];
    float ly = x[b * 8 + (idx / 9) * 2 + 1];
#pragma unroll
    for (int st = 0; st < 36; ++st) {
      int i = st / 9, j = st % 9;
      if (st <= tid && i * j == idx) { lx += c_shift[j][0]; ly += c_shift[j][1]; }
    }
    int rel = tid - pg * QP;
    if (rel >= 0 && rel < QP) {
      int ix = (int)rintf(lx * 255.f);
      int iy = (int)rintf((ly + 1.0f) * 255.f);
      s_ix[rel] = min(max(ix, 0), 255);
      s_iy[rel] = min(max(iy, 0), 255);
    }
  }
  __syncthreads();

  // ---- gather: seg-coalesced. lane-load = (q, c, h, seg) --------------------
  const float* db = d + (size_t)b * CCH * IMG;
#pragma unroll
  for (int u = 0; u < 7; ++u) {
    int rid = tid + u * NTHR;
    if (rid < SEGS) {
      int q    = rid / 792;            // 792 = 264*3
      int rem  = rid - q * 792;
      int c    = rem / 24;
      int hs   = rem - c * 24;
      int h    = hs / 3, seg = hs - h * 3;
      int r    = s_ix[q] - 4 + h;
      int col0 = s_iy[q] - 4;
      int a    = col0 & 3;
      int sb   = (col0 - a) + seg * 4;
      float4 v = {0.f, 0.f, 0.f, 0.f};
      if ((unsigned)r < 256u && (unsigned)sb < 256u)
        v = *(const float4*)(db + c * IMG + r * 256 + sb);
      int w0 = seg * 4 - a;
      float* dst = smemf + q * KSZ + c * 64 + h * 8;
      if ((unsigned)(w0 + 0) < 8u) dst[w0 + 0] = v.x;
      if ((unsigned)(w0 + 1) < 8u) dst[w0 + 1] = v.y;
      if ((unsigned)(w0 + 2) < 8u) dst[w0 + 2] = v.z;
      if ((unsigned)(w0 + 3) < 8u) dst[w0 + 3] = v.w;
    }
  }
  __syncthreads();

  // ---- conv: 8 chunks per half, 4 rows x 4 crops per warp -------------------
  const float4* w4 = (const float4*)conv_w;
  const int c0 = half * 8;

  float acc[4][QP];
#pragma unroll
  for (int j = 0; j < 4; ++j)
#pragma unroll
    for (int q = 0; q < QP; ++q) acc[j][q] = 0.f;

#pragma unroll 2
  for (int c = 0; c < 8; ++c) {
    int k4 = lane + (c0 + c) * 32;
    float4 wv[4];
#pragma unroll
    for (int j = 0; j < 4; ++j) wv[j] = __ldg(w4 + (rg + j * 8) * 528 + k4);
    float4 cv[QP];
#pragma unroll
    for (int q = 0; q < QP; ++q)
      cv[q] = *(const float4*)(smemf + q * KSZ + k4 * 4);
#pragma unroll
    for (int j = 0; j < 4; ++j)
#pragma unroll
      for (int q = 0; q < QP; ++q) {
        acc[j][q] = fmaf(cv[q].x, wv[j].x, acc[j][q]);
        acc[j][q] = fmaf(cv[q].y, wv[j].y, acc[j][q]);
        acc[j][q] = fmaf(cv[q].z, wv[j].z, acc[j][q]);
        acc[j][q] = fmaf(cv[q].w, wv[j].w, acc[j][q]);
      }
  }
  if (half == 1 && lane < 16) {        // epilogue chunk 16: k4 in [512,528)
    int k4 = lane + 512;
    float4 wv[4];
#pragma unroll
    for (int j = 0; j < 4; ++j) wv[j] = __ldg(w4 + (rg + j * 8) * 528 + k4);
    float4 cv[QP];
#pragma unroll
    for (int q = 0; q < QP; ++q)
      cv[q] = *(const float4*)(smemf + q * KSZ + k4 * 4);
#pragma unroll
    for (int j = 0; j < 4; ++j)
#pragma unroll
      for (int q = 0; q < QP; ++q) {
        acc[j][q] = fmaf(cv[q].x, wv[j].x, acc[j][q]);
        acc[j][q] = fmaf(cv[q].y, wv[j].y, acc[j][q]);
        acc[j][q] = fmaf(cv[q].z, wv[j].z, acc[j][q]);
        acc[j][q] = fmaf(cv[q].w, wv[j].w, acc[j][q]);
      }
  }

  // ---- row 32: small second loop on rg==0 warps (disjoint reg lifetime) -----
  float a32[QP];
#pragma unroll
  for (int q = 0; q < QP; ++q) a32[q] = 0.f;
  if (rg == 0) {
    for (int c = 0; c < 8; ++c) {
      int k4 = lane + (c0 + c) * 32;
      float4 wx = __ldg(w4 + 32 * 528 + k4);
#pragma unroll
      for (int q = 0; q < QP; ++q) {
        float4 cv = *(const float4*)(smemf + q * KSZ + k4 * 4);
        a32[q] = fmaf(cv.x, wx.x, a32[q]);
        a32[q] = fmaf(cv.y, wx.y, a32[q]);
        a32[q] = fmaf(cv.z, wx.z, a32[q]);
        a32[q] = fmaf(cv.w, wx.w, a32[q]);
      }
    }
    if (half == 1 && lane < 16) {
      int k4 = lane + 512;
      float4 wx = __ldg(w4 + 32 * 528 + k4);
#pragma unroll
      for (int q = 0; q < QP; ++q) {
        float4 cv = *(const float4*)(smemf + q * KSZ + k4 * 4);
        a32[q] = fmaf(cv.x, wx.x, a32[q]);
        a32[q] = fmaf(cv.y, wx.y, a32[q]);
        a32[q] = fmaf(cv.z, wx.z, a32[q]);
        a32[q] = fmaf(cv.w, wx.w, a32[q]);
      }
    }
  }

  // ---- intra-warp reduce; half1 stages to smem ------------------------------
#pragma unroll
  for (int j = 0; j < 4; ++j)
#pragma unroll
    for (int q = 0; q < QP; ++q) {
      float s = acc[j][q];
#pragma unroll
      for (int sh = 16; sh; sh >>= 1) s += __shfl_xor_sync(0xffffffffu, s, sh);
      acc[j][q] = s;
      if (half == 1 && lane == 0) s_part[(rg + j * 8) * QP + q] = s;
    }
#pragma unroll
  for (int q = 0; q < QP; ++q) {
    float s = a32[q];
#pragma unroll
    for (int sh = 16; sh; sh >>= 1) s += __shfl_xor_sync(0xffffffffu, s, sh);
    a32[q] = s;
    if (warp == 8 && lane == 0) s_part32[q] = s;
  }
  __syncthreads();

  // ---- half0 combines + writes patch_feat ----------------------------------
  float* pfb = g_patch_feat + ((size_t)b * 36 + pg * QP) * 33;
  if (half == 0 && lane == 0) {
#pragma unroll
    for (int j = 0; j < 4; ++j) {
      int o = rg + j * 8;
#pragma unroll
      for (int q = 0; q < QP; ++q)
        pfb[q * 33 + o] = acc[j][q] + s_part[o * QP + q] + conv_b[o];
    }
    if (warp == 0) {
#pragma unroll
      for (int q = 0; q < QP; ++q)
        pfb[q * 33 + 32] = a32[q] + s_part32[q] + conv_b[32];
    }
  }

  // ---- last-block-per-batch election ---------------------------------------
  __threadfence();
  __syncthreads();
  if (tid == 0) {
    int old = atomicAdd(&g_cnt[b], 1);
    s_flag = ((old % NPG) == (NPG - 1)) ? 1 : 0;
  }
  __syncthreads();
  if (!s_flag) return;

  // ======================= TAIL (winner block per batch) =====================
  float* gin = smemf;                 // [0, 3852)
  float* psm = smemf + 3872;          // params: 1924 floats
  float* lhv = smemf + 5800;          // 72
  float* Am  = smemf + 5880;          // 64
  float* M1m = smemf + 5944;          // 144  (ends 6088 < 8448)

  uint32_t k10, k11, k20, k21;
  threefry2x32(0u, 42u, 0u, 0u, k10, k11);
  threefry2x32(0u, 42u, 0u, 1u, k20, k21);

  // phase 1: params + lh + patch_feat->gin (independent)
  for (int e = tid; e < 144; e += NTHR) psm[e] = T[e];
  for (int e = tid; e < 576; e += NTHR) psm[144 + e] = H[e];
  if (tid < 16)  psm[720 + tid] = W[tid];
  for (int e = tid; e < 214; e += NTHR) psm[736 + e] = l1w[e];
  if (tid < 2)   psm[950 + tid] = l1b[tid];
  for (int e = tid; e < 963; e += NTHR) psm[952 + e] = l2w[e];
  if (tid < 9)   psm[1915 + tid] = l2b[tid];

  if (tid < 36) {
    float lx = x[b * 8 + (tid / 9) * 2 + 0];
    float ly = x[b * 8 + (tid / 9) * 2 + 1];
#pragma unroll
    for (int st = 0; st < 36; ++st) {
      int i = st / 9, j = st % 9;
      if (i * j == tid) { lx += c_shift[j][0]; ly += c_shift[j][1]; }
    }
    lhv[tid * 2 + 0] = lx; lhv[tid * 2 + 1] = ly;
    gin[tid * FEAT + 105] = lx;
    gin[tid * FEAT + 106] = ly;
  }
  for (int e = tid; e < 1188; e += NTHR)
    gin[(e / 33) * FEAT + (e % 33)] = __ldcg(&g_patch_feat[b * 1188 + e]);
  __syncthreads();

  // phase 2: shape feats + A
  for (int e = tid; e < 36 * 72; e += NTHR) {
    int n = e / 72, qq = e % 72, m = qq >> 1, kk = qq & 1;
    gin[n * FEAT + 33 + qq] = lhv[m * 2 + kk] - lhv[n * 2 + kk];
  }
  if (tid >= 64 && tid < 128) {
    int p = (tid - 64) >> 4, h = (tid - 64) & 15;
    float wh = psm[720 + h], s = 0.f;
    for (int n = 0; n < 36; ++n) s += psm[p * 36 + n] * (psm[144 + n * 16 + h] * wh);
    Am[p * 16 + h] = s;
  }
  __syncthreads();

  // phase 3: M1
  if (tid < 144) {
    int p = tid / 36, n = tid % 36;
    float s = 0.f;
#pragma unroll
    for (int h = 0; h < 16; ++h) s += Am[p * 16 + h] * psm[144 + n * 16 + h];
    M1m[p * 36 + n] = s;
  }
  __syncthreads();

  // phase 4: message + dropout + heads (warp p = point p)
  if (warp < 4) {
    const int p = warp;
    float hacc[11];
#pragma unroll
    for (int o = 0; o < 11; ++o) hacc[o] = 0.f;
#pragma unroll
    for (int r = 0; r < 4; ++r) {
      int f = lane + 32 * r;
      if (f < FEAT) {
        float s = 0.f;
#pragma unroll
        for (int n = 0; n < 36; ++n) s = fmaf(M1m[p * 36 + n], gin[n * FEAT + f], s);
        uint32_t g = (uint32_t)((b * 4 + p) * FEAT + f);
        float u1 = tf_uniform(k10, k11, g);
        float u2 = tf_uniform(k20, k21, g);
        float x1 = (u1 < 0.9f) ? s / 0.9f : 0.f;
        float x2 = (u2 < 0.9f) ? s / 0.9f : 0.f;
        hacc[0] = fmaf(x1, psm[736 + f], hacc[0]);
        hacc[1] = fmaf(x1, psm[736 + FEAT + f], hacc[1]);
#pragma unroll
        for (int j = 0; j < 9; ++j)
          hacc[2 + j] = fmaf(x2, psm[952 + j * FEAT + f], hacc[2 + j]);
      }
    }
#pragma unroll
    for (int o = 0; o < 11; ++o)
#pragma unroll
      for (int sh = 16; sh; sh >>= 1)
        hacc[o] += __shfl_xor_sync(0xffffffffu, hacc[o], sh);

    if (lane == 0) {
      float off0 = 1.f / (1.f + expf(-(hacc[0] + psm[950])));
      float off1 = 1.f / (1.f + expf(-(hacc[1] + psm[951])));
      float lg[9], mx = -1e30f;
#pragma unroll
      for (int j = 0; j < 9; ++j) { lg[j] = hacc[2 + j] + psm[1915 + j]; mx = fmaxf(mx, lg[j]); }
      float den = 0.f, s0 = 0.f, s1 = 0.f;
#pragma unroll
      for (int j = 0; j < 9; ++j) {
        float e = expf(lg[j] - mx);
        den += e;
        s0 += e * c_shift[j][0];
        s1 += e * c_shift[j][1];
      }
      s0 /= den; s1 /= den;
      out[b * 8 + p * 2 + 0] = (x[b * 8 + p * 2 + 0] + off0 * s0) * 255.f;
      out[b * 8 + p * 2 + 1] = (x[b * 8 + p * 2 + 1] + off1 * s1) * 255.f;
    }
  }
}

// ---------------------------------------------------------------------------
extern "C" void kernel_launch(void* const* d_in, const int* in_sizes, int n_in,
                              void* d_out, int out_size)
{
  const float* d      = (const float*)d_in[0];
  const float* x      = (const float*)d_in[1];
  const float* conv_w = (const float*)d_in[2];
  const float* conv_b = (const float*)d_in[3];
  const float* H      = (const float*)d_in[4];
  const float* T      = (const float*)d_in[5];
  const float* W      = (const float*)d_in[6];
  const float* l1w    = (const float*)d_in[7];
  const float* l1b    = (const float*)d_in[8];
  const float* l2w    = (const float*)d_in[9];
  const float* l2b    = (const float*)d_in[10];
  float* out = (float*)d_out;

  dim3 grid(NPG, 32);
  fused_kernel<<<grid, NTHR>>>(d, x, conv_w, conv_b,
                               H, T, W, l1w, l1b, l2w, l2b, out);
}

// round 11
// speedup vs baseline: 1.1001x; 1.0695x over previous
#include <cuda_runtime.h>
#include <cstdint>

#define CCH    33
#define KSZ    2112      // 33*8*8 floats per crop
#define FEAT   107
#define IMG    65536     // 256*256
#define QP     4         // crops per block
#define NPG    9         // patch groups (36/QP)
#define NTHR   512
#define SEGS   (QP * CCH * 8 * 3)      // 3168 lane-loads (3 segs per row)

// SHIFTS / 255 exactly as the reference table (note duplicated [0,8] at j=6)
__constant__ float c_shift[9][2] = {
  {-8.f/255.f,  0.f/255.f}, {-8.f/255.f,  8.f/255.f}, { 0.f/255.f,  8.f/255.f},
  { 8.f/255.f,  8.f/255.f}, { 8.f/255.f,  0.f/255.f}, { 8.f/255.f, -8.f/255.f},
  { 0.f/255.f,  8.f/255.f}, {-8.f/255.f, -8.f/255.f}, { 0.f/255.f,  0.f/255.f}
};

__device__ float g_patch_feat[32 * 36 * 33];
__device__ int   g_cnt[32];            // monotonic; %NPG==NPG-1 triggers tail

// ---------------------------------------------------------------------------
// threefry2x32 (JAX partitionable)
// ---------------------------------------------------------------------------
__device__ __forceinline__ void threefry2x32(uint32_t k0, uint32_t k1,
                                             uint32_t x0, uint32_t x1,
                                             uint32_t& o0, uint32_t& o1)
{
  uint32_t ks[3] = {k0, k1, k0 ^ k1 ^ 0x1BD11BDAu};
  x0 += ks[0]; x1 += ks[1];
  const int R[2][4] = {{13, 15, 26, 6}, {17, 29, 16, 24}};
#pragma unroll
  for (int i = 0; i < 5; ++i) {
#pragma unroll
    for (int r = 0; r < 4; ++r) {
      x0 += x1;
      int rr = R[i & 1][r];
      x1 = (x1 << rr) | (x1 >> (32 - rr));
      x1 ^= x0;
    }
    x0 += ks[(i + 1) % 3];
    x1 += ks[(i + 2) % 3] + (uint32_t)(i + 1);
  }
  o0 = x0; o1 = x1;
}

__device__ __forceinline__ float tf_uniform(uint32_t k0, uint32_t k1, uint32_t g)
{
  uint32_t y0, y1;
  threefry2x32(k0, k1, 0u, g, y0, y1);
  uint32_t bits = y0 ^ y1;
  return __uint_as_float((bits >> 9) | 0x3f800000u) - 1.0f;
}

// ---------------------------------------------------------------------------
// Fused kernel. grid (NPG, 32) x 512 threads.
// 16 warps = 8 row-groups x 2 K-halves. rg owns rows {rg,rg+8,rg+16,rg+24}.
// ---------------------------------------------------------------------------
__global__ __launch_bounds__(NTHR, 2)
void fused_kernel(const float* __restrict__ d, const float* __restrict__ x,
                  const float* __restrict__ conv_w, const float* __restrict__ conv_b,
                  const float* __restrict__ H,  const float* __restrict__ T,
                  const float* __restrict__ W,
                  const float* __restrict__ l1w, const float* __restrict__ l1b,
                  const float* __restrict__ l2w, const float* __restrict__ l2b,
                  float* __restrict__ out)
{
  __shared__ float smemf[QP * KSZ];    // crops; aliased by tail
  __shared__ float s_part[33 * QP];    // half-1 partials
  __shared__ float s_part32[QP];
  __shared__ int s_ix[QP], s_iy[QP];
  __shared__ int s_flag;

  const int pg  = blockIdx.x;
  const int b   = blockIdx.y;
  const int tid = threadIdx.x;
  const int warp = tid >> 5, lane = tid & 31;
  const int rg   = warp & 7, half = warp >> 3;

  // ---- crop coordinates (parallel replay, exact fp order) -------------------
  if (tid < 36) {
    const int idx = (tid / 9) * (tid % 9);
    float lx = x[b * 8 + (idx / 9) * 2 + 0];
    float ly = x[b * 8 + (idx / 9) * 2 + 1];
#pragma unroll
    for (int st = 0; st < 36; ++st) {
      int i = st / 9, j = st % 9;
      if (st <= tid && i * j == idx) { lx += c_shift[j][0]; ly += c_shift[j][1]; }
    }
    int rel = tid - pg * QP;
    if (rel >= 0 && rel < QP) {
      int ix = (int)rintf(lx * 255.f);
      int iy = (int)rintf((ly + 1.0f) * 255.f);
      s_ix[rel] = min(max(ix, 0), 255);
      s_iy[rel] = min(max(iy, 0), 255);
    }
  }
  __syncthreads();

  // ---- gather: seg-coalesced. lane-load = (q, c, h, seg) --------------------
  const float* db = d + (size_t)b * CCH * IMG;
#pragma unroll
  for (int u = 0; u < 7; ++u) {
    int rid = tid + u * NTHR;
    if (rid < SEGS) {
      int q    = rid / 792;            // 792 = 264*3
      int rem  = rid - q * 792;
      int c    = rem / 24;
      int hs   = rem - c * 24;
      int h    = hs / 3, seg = hs - h * 3;
      int r    = s_ix[q] - 4 + h;
      int col0 = s_iy[q] - 4;
      int a    = col0 & 3;
      int sb   = (col0 - a) + seg * 4;
      float4 v = {0.f, 0.f, 0.f, 0.f};
      if ((unsigned)r < 256u && (unsigned)sb < 256u)
        v = *(const float4*)(db + c * IMG + r * 256 + sb);
      int w0 = seg * 4 - a;
      float* dst = smemf + q * KSZ + c * 64 + h * 8;
      if ((unsigned)(w0 + 0) < 8u) dst[w0 + 0] = v.x;
      if ((unsigned)(w0 + 1) < 8u) dst[w0 + 1] = v.y;
      if ((unsigned)(w0 + 2) < 8u) dst[w0 + 2] = v.z;
      if ((unsigned)(w0 + 3) < 8u) dst[w0 + 3] = v.w;
    }
  }
  __syncthreads();

  // ---- conv: 8 chunks per half, 4 rows x 4 crops per warp -------------------
  const float4* w4 = (const float4*)conv_w;
  const int c0 = half * 8;

  float acc[4][QP];
#pragma unroll
  for (int j = 0; j < 4; ++j)
#pragma unroll
    for (int q = 0; q < QP; ++q) acc[j][q] = 0.f;

#pragma unroll 2
  for (int c = 0; c < 8; ++c) {
    int k4 = lane + (c0 + c) * 32;
    float4 wv[4];
#pragma unroll
    for (int j = 0; j < 4; ++j) wv[j] = __ldg(w4 + (rg + j * 8) * 528 + k4);
    float4 cv[QP];
#pragma unroll
    for (int q = 0; q < QP; ++q)
      cv[q] = *(const float4*)(smemf + q * KSZ + k4 * 4);
#pragma unroll
    for (int j = 0; j < 4; ++j)
#pragma unroll
      for (int q = 0; q < QP; ++q) {
        acc[j][q] = fmaf(cv[q].x, wv[j].x, acc[j][q]);
        acc[j][q] = fmaf(cv[q].y, wv[j].y, acc[j][q]);
        acc[j][q] = fmaf(cv[q].z, wv[j].z, acc[j][q]);
        acc[j][q] = fmaf(cv[q].w, wv[j].w, acc[j][q]);
      }
  }
  if (half == 1 && lane < 16) {        // epilogue chunk 16: k4 in [512,528)
    int k4 = lane + 512;
    float4 wv[4];
#pragma unroll
    for (int j = 0; j < 4; ++j) wv[j] = __ldg(w4 + (rg + j * 8) * 528 + k4);
    float4 cv[QP];
#pragma unroll
    for (int q = 0; q < QP; ++q)
      cv[q] = *(const float4*)(smemf + q * KSZ + k4 * 4);
#pragma unroll
    for (int j = 0; j < 4; ++j)
#pragma unroll
      for (int q = 0; q < QP; ++q) {
        acc[j][q] = fmaf(cv[q].x, wv[j].x, acc[j][q]);
        acc[j][q] = fmaf(cv[q].y, wv[j].y, acc[j][q]);
        acc[j][q] = fmaf(cv[q].z, wv[j].z, acc[j][q]);
        acc[j][q] = fmaf(cv[q].w, wv[j].w, acc[j][q]);
      }
  }

  // ---- row 32: small second loop on rg==0 warps (disjoint reg lifetime) -----
  float a32[QP];
#pragma unroll
  for (int q = 0; q < QP; ++q) a32[q] = 0.f;
  if (rg == 0) {
    for (int c = 0; c < 8; ++c) {
      int k4 = lane + (c0 + c) * 32;
      float4 wx = __ldg(w4 + 32 * 528 + k4);
#pragma unroll
      for (int q = 0; q < QP; ++q) {
        float4 cv = *(const float4*)(smemf + q * KSZ + k4 * 4);
        a32[q] = fmaf(cv.x, wx.x, a32[q]);
        a32[q] = fmaf(cv.y, wx.y, a32[q]);
        a32[q] = fmaf(cv.z, wx.z, a32[q]);
        a32[q] = fmaf(cv.w, wx.w, a32[q]);
      }
    }
    if (half == 1 && lane < 16) {
      int k4 = lane + 512;
      float4 wx = __ldg(w4 + 32 * 528 + k4);
#pragma unroll
      for (int q = 0; q < QP; ++q) {
        float4 cv = *(const float4*)(smemf + q * KSZ + k4 * 4);
        a32[q] = fmaf(cv.x, wx.x, a32[q]);
        a32[q] = fmaf(cv.y, wx.y, a32[q]);
        a32[q] = fmaf(cv.z, wx.z, a32[q]);
        a32[q] = fmaf(cv.w, wx.w, a32[q]);
      }
    }
  }

  // ---- intra-warp reduce; half1 stages to smem ------------------------------
#pragma unroll
  for (int j = 0; j < 4; ++j)
#pragma unroll
    for (int q = 0; q < QP; ++q) {
      float s = acc[j][q];
#pragma unroll
      for (int sh = 16; sh; sh >>= 1) s += __shfl_xor_sync(0xffffffffu, s, sh);
      acc[j][q] = s;
      if (half == 1 && lane == 0) s_part[(rg + j * 8) * QP + q] = s;
    }
#pragma unroll
  for (int q = 0; q < QP; ++q) {
    float s = a32[q];
#pragma unroll
    for (int sh = 16; sh; sh >>= 1) s += __shfl_xor_sync(0xffffffffu, s, sh);
    a32[q] = s;
    if (warp == 8 && lane == 0) s_part32[q] = s;
  }
  __syncthreads();

  // ---- half0 combines + writes patch_feat ----------------------------------
  float* pfb = g_patch_feat + ((size_t)b * 36 + pg * QP) * 33;
  if (half == 0 && lane == 0) {
#pragma unroll
    for (int j = 0; j < 4; ++j) {
      int o = rg + j * 8;
#pragma unroll
      for (int q = 0; q < QP; ++q)
        pfb[q * 33 + o] = acc[j][q] + s_part[o * QP + q] + conv_b[o];
    }
    if (warp == 0) {
#pragma unroll
      for (int q = 0; q < QP; ++q)
        pfb[q * 33 + 32] = a32[q] + s_part32[q] + conv_b[32];
    }
  }

  // ---- last-block-per-batch election ---------------------------------------
  __threadfence();
  __syncthreads();
  if (tid == 0) {
    int old = atomicAdd(&g_cnt[b], 1);
    s_flag = ((old % NPG) == (NPG - 1)) ? 1 : 0;
  }
  __syncthreads();
  if (!s_flag) return;

  // ======================= TAIL (winner block per batch) =====================
  float* gin = smemf;                 // [0, 3852)
  float* psm = smemf + 3872;          // params: 1924 floats
  float* lhv = smemf + 5800;          // 72
  float* Am  = smemf + 5880;          // 64
  float* M1m = smemf + 5944;          // 144  (ends 6088 < 8448)

  uint32_t k10, k11, k20, k21;
  threefry2x32(0u, 42u, 0u, 0u, k10, k11);
  threefry2x32(0u, 42u, 0u, 1u, k20, k21);

  // phase 1: params + lh + patch_feat->gin (independent)
  for (int e = tid; e < 144; e += NTHR) psm[e] = T[e];
  for (int e = tid; e < 576; e += NTHR) psm[144 + e] = H[e];
  if (tid < 16)  psm[720 + tid] = W[tid];
  for (int e = tid; e < 214; e += NTHR) psm[736 + e] = l1w[e];
  if (tid < 2)   psm[950 + tid] = l1b[tid];
  for (int e = tid; e < 963; e += NTHR) psm[952 + e] = l2w[e];
  if (tid < 9)   psm[1915 + tid] = l2b[tid];

  if (tid < 36) {
    float lx = x[b * 8 + (tid / 9) * 2 + 0];
    float ly = x[b * 8 + (tid / 9) * 2 + 1];
#pragma unroll
    for (int st = 0; st < 36; ++st) {
      int i = st / 9, j = st % 9;
      if (i * j == tid) { lx += c_shift[j][0]; ly += c_shift[j][1]; }
    }
    lhv[tid * 2 + 0] = lx; lhv[tid * 2 + 1] = ly;
    gin[tid * FEAT + 105] = lx;
    gin[tid * FEAT + 106] = ly;
  }
  for (int e = tid; e < 1188; e += NTHR)
    gin[(e / 33) * FEAT + (e % 33)] = __ldcg(&g_patch_feat[b * 1188 + e]);
  __syncthreads();

  // phase 2: shape feats + A
  for (int e = tid; e < 36 * 72; e += NTHR) {
    int n = e / 72, qq = e % 72, m = qq >> 1, kk = qq & 1;
    gin[n * FEAT + 33 + qq] = lhv[m * 2 + kk] - lhv[n * 2 + kk];
  }
  if (tid >= 64 && tid < 128) {
    int p = (tid - 64) >> 4, h = (tid - 64) & 15;
    float wh = psm[720 + h], s = 0.f;
    for (int n = 0; n < 36; ++n) s += psm[p * 36 + n] * (psm[144 + n * 16 + h] * wh);
    Am[p * 16 + h] = s;
  }
  __syncthreads();

  // phase 3: M1
  if (tid < 144) {
    int p = tid / 36, n = tid % 36;
    float s = 0.f;
#pragma unroll
    for (int h = 0; h < 16; ++h) s += Am[p * 16 + h] * psm[144 + n * 16 + h];
    M1m[p * 36 + n] = s;
  }
  __syncthreads();

  // phase 4: message + dropout + heads (warp p = point p)
  if (warp < 4) {
    const int p = warp;
    float hacc[11];
#pragma unroll
    for (int o = 0; o < 11; ++o) hacc[o] = 0.f;
#pragma unroll
    for (int r = 0; r < 4; ++r) {
      int f = lane + 32 * r;
      if (f < FEAT) {
        float s = 0.f;
#pragma unroll
        for (int n = 0; n < 36; ++n) s = fmaf(M1m[p * 36 + n], gin[n * FEAT + f], s);
        uint32_t g = (uint32_t)((b * 4 + p) * FEAT + f);
        float u1 = tf_uniform(k10, k11, g);
        float u2 = tf_uniform(k20, k21, g);
        float x1 = (u1 < 0.9f) ? s / 0.9f : 0.f;
        float x2 = (u2 < 0.9f) ? s / 0.9f : 0.f;
        hacc[0] = fmaf(x1, psm[736 + f], hacc[0]);
        hacc[1] = fmaf(x1, psm[736 + FEAT + f], hacc[1]);
#pragma unroll
        for (int j = 0; j < 9; ++j)
          hacc[2 + j] = fmaf(x2, psm[952 + j * FEAT + f], hacc[2 + j]);
      }
    }
#pragma unroll
    for (int o = 0; o < 11; ++o)
#pragma unroll
      for (int sh = 16; sh; sh >>= 1)
        hacc[o] += __shfl_xor_sync(0xffffffffu, hacc[o], sh);

    if (lane == 0) {
      float off0 = 1.f / (1.f + expf(-(hacc[0] + psm[950])));
      float off1 = 1.f / (1.f + expf(-(hacc[1] + psm[951])));
      float lg[9], mx = -1e30f;
#pragma unroll
      for (int j = 0; j < 9; ++j) { lg[j] = hacc[2 + j] + psm[1915 + j]; mx = fmaxf(mx, lg[j]); }
      float den = 0.f, s0 = 0.f, s1 = 0.f;
#pragma unroll
      for (int j = 0; j < 9; ++j) {
        float e = expf(lg[j] - mx);
        den += e;
        s0 += e * c_shift[j][0];
        s1 += e * c_shift[j][1];
      }
      s0 /= den; s1 /= den;
      out[b * 8 + p * 2 + 0] = (x[b * 8 + p * 2 + 0] + off0 * s0) * 255.f;
      out[b * 8 + p * 2 + 1] = (x[b * 8 + p * 2 + 1] + off1 * s1) * 255.f;
    }
  }
}

// ---------------------------------------------------------------------------
extern "C" void kernel_launch(void* const* d_in, const int* in_sizes, int n_in,
                              void* d_out, int out_size)
{
  const float* d      = (const float*)d_in[0];
  const float* x      = (const float*)d_in[1];
  const float* conv_w = (const float*)d_in[2];
  const float* conv_b = (const float*)d_in[3];
  const float* H      = (const float*)d_in[4];
  const float* T      = (const float*)d_in[5];
  const float* W      = (const float*)d_in[6];
  const float* l1w    = (const float*)d_in[7];
  const float* l1b    = (const float*)d_in[8];
  const float* l2w    = (const float*)d_in[9];
  const float* l2b    = (const float*)d_in[10];
  float* out = (float*)d_out;

  dim3 grid(NPG, 32);
  fused_kernel<<<grid, NTHR>>>(d, x, conv_w, conv_b,
                               H, T, W, l1w, l1b, l2w, l2b, out);
}